// round 14
// baseline (speedup 1.0000x reference)
#include <cuda_runtime.h>
#include <math.h>

#define BB 16
#define NN 131072
#define GG 16
#define BN (BB*NN)
#define NGB (BB*GG)          // 256 (b,g) pairs
#define NBLK 2048            // scatter blocks (128 per batch)
#define SPB  128             // slabs (scatter blocks) per batch
#define SBUF 6144            // smem key buffer (expected cnt ~4096, >30 sigma margin)
#define CCAP 2048            // candidate cap (expected ~300, huge margin)

// ---------------- scratch (device globals; zero at load, re-zeroed by finalizer) ----------------
__device__ unsigned g_keys[BN];          // per-block slabs of group-sorted keys (4KB each)
__device__ unsigned g_blkcnt[NBLK * GG]; // per-(block,group) counts (overwritten every launch)
__device__ unsigned g_mg[BN / 4];        // packed (valid<<4)|group, one byte/point
__device__ float    g_inv[NGB];          // 1 / clamp(|median|, eps)
__device__ double   g_psum[32];          // distributed loss partials
__device__ unsigned g_tcnt[32];          // distributed valid-count partials
__device__ unsigned g_done;              // loss block completion counter

// order-preserving map f32 -> u32 (ascending)
__device__ __forceinline__ unsigned key_of(float z) {
    unsigned u = __float_as_uint(z);
    return (u & 0x80000000u) ? ~u : (u | 0x80000000u);
}

// ---------------- K1: slab scatter, zero global coordination (proven 12.4us) ----------------
__global__ void k_scatter(const float* __restrict__ target, const int* __restrict__ mask,
                          const int* __restrict__ groups) {
    // release the dependent (select) launch as early as possible
    cudaTriggerProgrammaticLaunchCompletion();
    __shared__ unsigned s_cnt[32][16];     // slot = wid*4 + e
    __shared__ unsigned s_gstart[17];      // block-local group starts (+ total)
    __shared__ uint4    s_keys4[256];      // staged keys grouped by bucket (aliased)
    unsigned* s_keys = reinterpret_cast<unsigned*>(s_keys4);
    unsigned p0 = blockIdx.x * 1024u + threadIdx.x * 4u;  // 4 consecutive points/thread
    int wid = threadIdx.x >> 5, lane = threadIdx.x & 31;

    ((unsigned*)s_cnt)[threadIdx.x] = 0;
    ((unsigned*)s_cnt)[256 + threadIdx.x] = 0;

    int4 m4 = *reinterpret_cast<const int4*>(mask + p0);
    int4 g4 = *reinterpret_cast<const int4*>(groups + p0);
    const float4* tt = reinterpret_cast<const float4*>(target + 3u * p0);
    float4 t0 = tt[0], t1 = tt[1], t2 = tt[2];
    int   m[4] = {m4.x, m4.y, m4.z, m4.w};
    int   g[4] = {g4.x & 15, g4.y & 15, g4.z & 15, g4.w & 15};
    float z[4] = {t0.z, t1.y, t2.x, t2.w};

    unsigned mg = 0;
#pragma unroll
    for (int e = 0; e < 4; e++)
        mg |= ((m[e] ? 0x10u : 0u) | (unsigned)g[e]) << (8 * e);
    g_mg[p0 >> 2] = mg;
    __syncthreads();   // s_cnt zero visible

    unsigned peers[4];
#pragma unroll
    for (int e = 0; e < 4; e++) {
        unsigned tag = m[e] ? (unsigned)g[e] : 0xFFFFFFFFu;
        peers[e] = __match_any_sync(0xffffffffu, tag);
        if (m[e] && lane == (__ffs(peers[e]) - 1))
            s_cnt[wid * 4 + e][g[e]] = __popc(peers[e]);
    }
    __syncthreads();

    if (threadIdx.x < 16) {
        unsigned run = 0;
#pragma unroll
        for (int s = 0; s < 32; s++) {
            unsigned c = s_cnt[s][threadIdx.x];
            s_cnt[s][threadIdx.x] = run;
            run += c;
        }
        unsigned incl = run;
#pragma unroll
        for (int o = 1; o < 16; o <<= 1) {
            unsigned n = __shfl_up_sync(0x0000FFFFu, incl, o);
            if (lane >= o) incl += n;
        }
        s_gstart[threadIdx.x] = incl - run;
        if (threadIdx.x == 15) s_gstart[16] = incl;
        g_blkcnt[blockIdx.x * GG + threadIdx.x] = run;   // unconditional: no reset needed
    }
    __syncthreads();

#pragma unroll
    for (int e = 0; e < 4; e++) {
        if (m[e]) {
            unsigned local = s_gstart[g[e]] + s_cnt[wid * 4 + e][g[e]]
                           + __popc(peers[e] & ((1u << lane) - 1u));
            s_keys[local] = key_of(z[e]);
        }
    }
    __syncthreads();

    // straight coalesced copy of the staged (group-sorted) slab
    unsigned nvec = (s_gstart[16] + 3u) >> 2;
    uint4* dst = reinterpret_cast<uint4*>(g_keys + blockIdx.x * 1024u);
    for (unsigned i = threadIdx.x; i < nvec; i += 256u) dst[i] = s_keys4[i];
}

// ---------------- K2: fused gather + 2048-bin radix (11/11/10 bits) ----------------
__global__ void k_select() {
    // release the dependent (loss) launch immediately; loss pre-sync work touches
    // only harness inputs and g_mg (complete before this kernel started).
    cudaTriggerProgrammaticLaunchCompletion();
    __shared__ unsigned s_off[SPB], s_c[SPB], s_dst[SPB];
    __shared__ unsigned s_hist[2048];
    __shared__ unsigned s_wsum[16];
    __shared__ unsigned s_wt[4];
    __shared__ unsigned s_buf[SBUF];
    __shared__ unsigned s_cand[CCAP];
    __shared__ unsigned sh_sel, sh_k, sh_n, sh_app;
    int bg = blockIdx.x;
    int b = bg >> 4, g = bg & 15;
    int t = threadIdx.x, lane = t & 31, wid = t >> 5;

    // pre-sync prologue: zero the histogram (smem only)
    for (int i = t; i < 2048; i += 512) s_hist[i] = 0;

    // wait for scatter's outputs (g_blkcnt, g_keys) to be visible
    cudaGridDependencySynchronize();

    // per-slab run offset/count + destination prefix (128 slabs, warps 0..3)
    unsigned my_incl = 0, my_c = 0;
    if (t < SPB) {
        const uint4* p = reinterpret_cast<const uint4*>(g_blkcnt + (unsigned)(b * SPB + t) * GG);
        uint4 c0 = p[0], c1 = p[1], c2 = p[2], c3 = p[3];
        unsigned cc[16] = {c0.x, c0.y, c0.z, c0.w, c1.x, c1.y, c1.z, c1.w,
                           c2.x, c2.y, c2.z, c2.w, c3.x, c3.y, c3.z, c3.w};
        unsigned start = 0;
        for (int j = 0; j < g; j++) start += cc[j];   // g uniform across block
        my_c = cc[g];
        s_off[t] = start;
        s_c[t] = my_c;
        my_incl = my_c;
#pragma unroll
        for (int o = 1; o < 32; o <<= 1) {
            unsigned n = __shfl_up_sync(0xffffffffu, my_incl, o);
            if (lane >= o) my_incl += n;
        }
        if (lane == 31) s_wt[wid] = my_incl;
    }
    __syncthreads();
    if (t < SPB) {
        unsigned off = 0;
#pragma unroll
        for (int w = 0; w < 4; w++) off += (w < wid) ? s_wt[w] : 0u;
        s_dst[t] = off + my_incl - my_c;
    }
    __syncthreads();
    unsigned cnt = s_dst[SPB - 1] + s_c[SPB - 1];
    if (t == 0 && cnt) atomicAdd(&g_tcnt[bg & 31], cnt);
    if (cnt == 0) {
        if (t == 0) g_inv[bg] = 1.0f;
        return;
    }
    bool fits = (cnt <= SBUF);

    // fused gather + level-1 histogram (bins = key >> 21)
    for (int s = wid; s < SPB; s += 16) {
        unsigned c = s_c[s];
        const unsigned* src = g_keys + (unsigned)(b * SPB + s) * 1024u + s_off[s];
        unsigned d = s_dst[s];
        for (unsigned j = lane; j < c; j += 32u) {
            unsigned key = src[j];
            atomicAdd(&s_hist[key >> 21], 1u);
            unsigned d2 = d + j;
            if (d2 < SBUF) s_buf[d2] = key;
        }
    }
    __syncthreads();

    // scan + pick helper over s_hist (nbins = 2048 or 1024), rank kk
    auto scan_pick = [&](int nbins, unsigned kk) {
        int per = nbins >> 9;                 // 4 or 2 bins per thread
        unsigned hh[4] = {0u, 0u, 0u, 0u};
        unsigned sum = 0;
        for (int j = 0; j < per; j++) { hh[j] = s_hist[t * per + j]; sum += hh[j]; }
        unsigned incl = sum;
#pragma unroll
        for (int o = 1; o < 32; o <<= 1) {
            unsigned n = __shfl_up_sync(0xffffffffu, incl, o);
            if (lane >= o) incl += n;
        }
        if (lane == 31) s_wsum[wid] = incl;
        __syncthreads();
        unsigned off = 0;
#pragma unroll
        for (int w = 0; w < 16; w++) off += (w < wid) ? s_wsum[w] : 0u;
        incl += off;
        unsigned excl = incl - sum;
        if (kk >= excl && kk < incl) {
            unsigned r = kk - excl;
            for (int j = 0; j < per; j++) {
                if (r < hh[j]) { sh_sel = (unsigned)(t * per + j); sh_k = r; sh_n = hh[j]; break; }
                r -= hh[j];
            }
        }
        __syncthreads();
    };

    unsigned k = (cnt - 1u) >> 1;            // lower median rank
    scan_pick(2048, k);
    unsigned sel0 = sh_sel; k = sh_k;
    unsigned ncand = sh_n;
    bool fits2 = (ncand <= CCAP);

    // collect candidates with top-11 == sel0 (ballot append)
    if (t == 0) sh_app = 0;
    __syncthreads();
    if (fits2) {
        if (fits) {
            unsigned lim = (cnt + 511u) & ~511u;
            for (unsigned i = t; i < lim; i += 512u) {
                bool ok = (i < cnt) && ((s_buf[i] >> 21) == sel0);
                unsigned key = ok ? s_buf[i] : 0u;
                unsigned bal = __ballot_sync(0xffffffffu, ok);
                unsigned base = 0;
                if (lane == 0 && bal) base = atomicAdd(&sh_app, (unsigned)__popc(bal));
                base = __shfl_sync(0xffffffffu, base, 0);
                if (ok) s_cand[base + __popc(bal & ((1u << lane) - 1u))] = key;
            }
        } else {
            for (int s = wid; s < SPB; s += 16) {
                unsigned c = s_c[s];
                const unsigned* src = g_keys + (unsigned)(b * SPB + s) * 1024u + s_off[s];
                unsigned lim = (c + 31u) & ~31u;
                for (unsigned j = lane; j < lim; j += 32u) {
                    bool ok = (j < c) && ((src[j] >> 21) == sel0);
                    unsigned key = ok ? src[j] : 0u;
                    unsigned bal = __ballot_sync(0xffffffffu, ok);
                    unsigned base = 0;
                    if (lane == 0 && bal) base = atomicAdd(&sh_app, (unsigned)__popc(bal));
                    base = __shfl_sync(0xffffffffu, base, 0);
                    if (ok) s_cand[base + __popc(bal & ((1u << lane) - 1u))] = key;
                }
            }
        }
    }
    __syncthreads();

    // level 2: bins = (key >> 10) & 2047 among candidates
    for (int i = t; i < 2048; i += 512) s_hist[i] = 0;
    __syncthreads();
    if (fits2) {
        for (unsigned i = t; i < ncand; i += 512u)
            atomicAdd(&s_hist[(s_cand[i] >> 10) & 2047u], 1u);
    } else if (fits) {
        for (unsigned i = t; i < cnt; i += 512u) {
            unsigned key = s_buf[i];
            if ((key >> 21) == sel0) atomicAdd(&s_hist[(key >> 10) & 2047u], 1u);
        }
    } else {
        for (int s = wid; s < SPB; s += 16) {
            unsigned c = s_c[s];
            const unsigned* src = g_keys + (unsigned)(b * SPB + s) * 1024u + s_off[s];
            for (unsigned j = lane; j < c; j += 32u) {
                unsigned key = src[j];
                if ((key >> 21) == sel0) atomicAdd(&s_hist[(key >> 10) & 2047u], 1u);
            }
        }
    }
    __syncthreads();
    scan_pick(2048, k);
    unsigned sel1 = sh_sel; k = sh_k;
    unsigned pfx22 = (sel0 << 11) | sel1;    // top 22 bits of the median key

    // level 3: bins = key & 1023 among candidates with (key >> 10) == pfx22
    for (int i = t; i < 1024; i += 512) s_hist[i] = 0;
    __syncthreads();
    if (fits2) {
        for (unsigned i = t; i < ncand; i += 512u) {
            unsigned key = s_cand[i];
            if ((key >> 10) == pfx22) atomicAdd(&s_hist[key & 1023u], 1u);
        }
    } else if (fits) {
        for (unsigned i = t; i < cnt; i += 512u) {
            unsigned key = s_buf[i];
            if ((key >> 10) == pfx22) atomicAdd(&s_hist[key & 1023u], 1u);
        }
    } else {
        for (int s = wid; s < SPB; s += 16) {
            unsigned c = s_c[s];
            const unsigned* src = g_keys + (unsigned)(b * SPB + s) * 1024u + s_off[s];
            for (unsigned j = lane; j < c; j += 32u) {
                unsigned key = src[j];
                if ((key >> 10) == pfx22) atomicAdd(&s_hist[key & 1023u], 1u);
            }
        }
    }
    __syncthreads();
    scan_pick(1024, k);

    if (t == 0) {
        unsigned kk = (pfx22 << 10) | sh_sel;
        unsigned ub = (kk & 0x80000000u) ? (kk & 0x7fffffffu) : ~kk;
        float med = __uint_as_float(ub);
        if (!isfinite(med)) med = 1.0f;      // nan_to_num semantics
        float ns = fmaxf(fabsf(med), 1e-6f);
        g_inv[bg] = 1.0f / ns;
    }
}

// ---------------- K3: branchless fused loss; PDL preload overlaps k_select ----------------
__global__ void k_loss(const float* __restrict__ pred, const float* __restrict__ target,
                       float* __restrict__ out) {
    __shared__ float sinv2[32];              // [0..15]=0 (invalid), [16..31]=1/norm
    __shared__ float swarp[8];
    __shared__ int s_flag;
    int b = blockIdx.x >> 7;
    unsigned p0 = blockIdx.x * 1024u + threadIdx.x * 4u;   // 4 consecutive points/thread

    // ---- pre-sync preload: inputs + g_mg (written by scatter, complete before select) ----
    unsigned mg = __ldg(&g_mg[p0 >> 2]);
    const float4* pp = reinterpret_cast<const float4*>(pred + 3u * p0);
    const float4* tt = reinterpret_cast<const float4*>(target + 3u * p0);
    float4 pa = pp[0], pb = pp[1], pc = pp[2];
    float4 ta = tt[0], tb = tt[1], tc = tt[2];

    // ---- wait for k_select's g_inv ----
    cudaGridDependencySynchronize();
    if (threadIdx.x < 32)
        sinv2[threadIdx.x] = (threadIdx.x >= 16) ? g_inv[b * GG + (threadIdx.x & 15)] : 0.f;
    __syncthreads();

    float pr[12] = {pa.x, pa.y, pa.z, pa.w, pb.x, pb.y, pb.z, pb.w, pc.x, pc.y, pc.z, pc.w};
    float tr[12] = {ta.x, ta.y, ta.z, ta.w, tb.x, tb.y, tb.z, tb.w, tc.x, tc.y, tc.z, tc.w};
    float acc = 0.f;
#pragma unroll
    for (int e = 0; e < 4; e++) {
        float inv = sinv2[(mg >> (8 * e)) & 0xFFu];   // 0 for invalid -> contributes 0
#pragma unroll
        for (int c = 0; c < 3; c++) {
            float p = pr[e * 3 + c] * inv;
            float t = tr[e * 3 + c] * inv;
            float u = fabsf(p); if (!(u <= 3.0e38f)) u = 0.f;   // nan_to_num
            float v = fabsf(t); if (!(v <= 3.0e38f)) v = 0.f;
            // |s_p*log1p(u) - s_t*log1p(v)| : same sign -> |log((1+u)/(1+v))|, diff -> log((1+u)(1+v))
            float a = 1.f + u, q = 1.f + v;
            bool same = (__float_as_uint(p) >> 31) == (__float_as_uint(t) >> 31);
            float r = same ? __fdividef(a, q) : a * q;
            acc += fabsf(__logf(r));
        }
    }
#pragma unroll
    for (int o = 16; o; o >>= 1) acc += __shfl_down_sync(0xffffffffu, acc, o);
    if ((threadIdx.x & 31) == 0) swarp[threadIdx.x >> 5] = acc;
    __syncthreads();
    if (threadIdx.x == 0) {
        float s = 0.f;
#pragma unroll
        for (int w = 0; w < 8; w++) s += swarp[w];
        atomicAdd(&g_psum[blockIdx.x & 31], (double)s);
        __threadfence();
        unsigned d = atomicAdd(&g_done, 1u);
        s_flag = (d == gridDim.x - 1u);
    }
    __syncthreads();
    if (s_flag) {
        if (threadIdx.x == 0) {
            unsigned total = 0;
#pragma unroll
            for (int j = 0; j < 32; j++) total += g_tcnt[j];
            double ssum = 0.0;
#pragma unroll
            for (int j = 0; j < 32; j++) ssum += g_psum[j];
            out[0] = (float)(ssum / (3.0 * (double)total + 1e-6));
        }
        __syncthreads();
        // restore scratch to all-zero for the next (graph-replayed) launch
        if (threadIdx.x < 32) { g_psum[threadIdx.x] = 0.0; g_tcnt[threadIdx.x] = 0u; }
        if (threadIdx.x == 0) g_done = 0u;
    }
}

extern "C" void kernel_launch(void* const* d_in, const int* in_sizes, int n_in,
                              void* d_out, int out_size) {
    const float* pred   = (const float*)d_in[0];
    const float* target = (const float*)d_in[1];
    const int*   mask   = (const int*)d_in[2];
    const int*   groups = (const int*)d_in[3];
    float* out = (float*)d_out;
    (void)in_sizes; (void)n_in; (void)out_size;

    k_scatter<<<NBLK, 256>>>(target, mask, groups);

    cudaLaunchAttribute attr[1];
    attr[0].id = cudaLaunchAttributeProgrammaticStreamSerialization;
    attr[0].val.programmaticStreamSerializationAllowed = 1;

    {   // k_select with PDL (overlaps scatter tail / launch gap)
        cudaLaunchConfig_t cfg = {};
        cfg.gridDim = dim3(NGB, 1, 1);
        cfg.blockDim = dim3(512, 1, 1);
        cfg.dynamicSmemBytes = 0;
        cfg.stream = 0;
        cfg.attrs = attr;
        cfg.numAttrs = 1;
        cudaLaunchKernelEx(&cfg, k_select);
    }
    {   // k_loss with PDL (preloads 52MB stream while select runs)
        cudaLaunchConfig_t cfg = {};
        cfg.gridDim = dim3(NBLK, 1, 1);
        cfg.blockDim = dim3(256, 1, 1);
        cfg.dynamicSmemBytes = 0;
        cfg.stream = 0;
        cfg.attrs = attr;
        cfg.numAttrs = 1;
        cudaLaunchKernelEx(&cfg, k_loss, pred, target, out);
    }
}

// round 16
// speedup vs baseline: 1.0653x; 1.0653x over previous
#include <cuda_runtime.h>
#include <math.h>

#define BB 16
#define NN 131072
#define GG 16
#define BN (BB*NN)
#define NGB (BB*GG)          // 256 (b,g) pairs
#define NBLK 2048            // scatter blocks (128 per batch)
#define SPB  128             // slabs (scatter blocks) per batch
#define SBUF 6144            // smem key buffer (expected cnt ~4096, >30 sigma margin)
#define CCAP 2048            // candidate cap (expected ~300, huge margin)

// ---------------- scratch (device globals; zero at load, re-zeroed by finalizer) ----------------
__device__ unsigned g_keys[BN];          // per-block slabs of group-sorted keys (4KB each)
__device__ unsigned g_blkcnt[NBLK * GG]; // per-(block,group) counts (overwritten every launch)
__device__ unsigned g_mg[BN / 4];        // packed (valid<<4)|group, one byte/point
__device__ float    g_inv[NGB];          // 1 / clamp(|median|, eps)
__device__ double   g_psum[32];          // distributed loss partials
__device__ unsigned g_tcnt[32];          // distributed valid-count partials
__device__ unsigned g_done;              // loss block completion counter

// order-preserving map f32 -> u32 (ascending)
__device__ __forceinline__ unsigned key_of(float z) {
    unsigned u = __float_as_uint(z);
    return (u & 0x80000000u) ? ~u : (u | 0x80000000u);
}

// ---------------- K1: slab scatter, zero global coordination (proven 12.4us) ----------------
__global__ void k_scatter(const float* __restrict__ target, const int* __restrict__ mask,
                          const int* __restrict__ groups) {
    __shared__ unsigned s_cnt[32][16];     // slot = wid*4 + e
    __shared__ unsigned s_gstart[17];      // block-local group starts (+ total)
    __shared__ uint4    s_keys4[256];      // staged keys grouped by bucket (aliased)
    unsigned* s_keys = reinterpret_cast<unsigned*>(s_keys4);
    unsigned p0 = blockIdx.x * 1024u + threadIdx.x * 4u;  // 4 consecutive points/thread
    int wid = threadIdx.x >> 5, lane = threadIdx.x & 31;

    ((unsigned*)s_cnt)[threadIdx.x] = 0;
    ((unsigned*)s_cnt)[256 + threadIdx.x] = 0;

    int4 m4 = *reinterpret_cast<const int4*>(mask + p0);
    int4 g4 = *reinterpret_cast<const int4*>(groups + p0);
    const float4* tt = reinterpret_cast<const float4*>(target + 3u * p0);
    float4 t0 = tt[0], t1 = tt[1], t2 = tt[2];
    int   m[4] = {m4.x, m4.y, m4.z, m4.w};
    int   g[4] = {g4.x & 15, g4.y & 15, g4.z & 15, g4.w & 15};
    float z[4] = {t0.z, t1.y, t2.x, t2.w};

    unsigned mg = 0;
#pragma unroll
    for (int e = 0; e < 4; e++)
        mg |= ((m[e] ? 0x10u : 0u) | (unsigned)g[e]) << (8 * e);
    g_mg[p0 >> 2] = mg;
    __syncthreads();   // s_cnt zero visible

    unsigned peers[4];
#pragma unroll
    for (int e = 0; e < 4; e++) {
        unsigned tag = m[e] ? (unsigned)g[e] : 0xFFFFFFFFu;
        peers[e] = __match_any_sync(0xffffffffu, tag);
        if (m[e] && lane == (__ffs(peers[e]) - 1))
            s_cnt[wid * 4 + e][g[e]] = __popc(peers[e]);
    }
    __syncthreads();

    if (threadIdx.x < 16) {
        unsigned run = 0;
#pragma unroll
        for (int s = 0; s < 32; s++) {
            unsigned c = s_cnt[s][threadIdx.x];
            s_cnt[s][threadIdx.x] = run;
            run += c;
        }
        unsigned incl = run;
#pragma unroll
        for (int o = 1; o < 16; o <<= 1) {
            unsigned n = __shfl_up_sync(0x0000FFFFu, incl, o);
            if (lane >= o) incl += n;
        }
        s_gstart[threadIdx.x] = incl - run;
        if (threadIdx.x == 15) s_gstart[16] = incl;
        g_blkcnt[blockIdx.x * GG + threadIdx.x] = run;   // unconditional: no reset needed
    }
    __syncthreads();

#pragma unroll
    for (int e = 0; e < 4; e++) {
        if (m[e]) {
            unsigned local = s_gstart[g[e]] + s_cnt[wid * 4 + e][g[e]]
                           + __popc(peers[e] & ((1u << lane) - 1u));
            s_keys[local] = key_of(z[e]);
        }
    }
    __syncthreads();

    // straight coalesced copy of the staged (group-sorted) slab
    unsigned nvec = (s_gstart[16] + 3u) >> 2;
    uint4* dst = reinterpret_cast<uint4*>(g_keys + blockIdx.x * 1024u);
    for (unsigned i = threadIdx.x; i < nvec; i += 256u) dst[i] = s_keys4[i];
}

// ---------------- K2: fused gather + 2048-bin radix (11/11/10 bits) ----------------
__global__ void k_select() {
    __shared__ unsigned s_off[SPB], s_c[SPB], s_dst[SPB];
    __shared__ unsigned s_hist[2048];
    __shared__ unsigned s_wsum[16];
    __shared__ unsigned s_wt[4];
    __shared__ unsigned s_buf[SBUF];
    __shared__ unsigned s_cand[CCAP];
    __shared__ unsigned sh_sel, sh_k, sh_n, sh_app;
    int bg = blockIdx.x;
    int b = bg >> 4, g = bg & 15;
    int t = threadIdx.x, lane = t & 31, wid = t >> 5;

    // per-slab run offset/count + destination prefix (128 slabs, warps 0..3)
    unsigned my_incl = 0, my_c = 0;
    if (t < SPB) {
        const uint4* p = reinterpret_cast<const uint4*>(g_blkcnt + (unsigned)(b * SPB + t) * GG);
        uint4 c0 = p[0], c1 = p[1], c2 = p[2], c3 = p[3];
        unsigned cc[16] = {c0.x, c0.y, c0.z, c0.w, c1.x, c1.y, c1.z, c1.w,
                           c2.x, c2.y, c2.z, c2.w, c3.x, c3.y, c3.z, c3.w};
        unsigned start = 0;
        for (int j = 0; j < g; j++) start += cc[j];   // g uniform across block
        my_c = cc[g];
        s_off[t] = start;
        s_c[t] = my_c;
        my_incl = my_c;
#pragma unroll
        for (int o = 1; o < 32; o <<= 1) {
            unsigned n = __shfl_up_sync(0xffffffffu, my_incl, o);
            if (lane >= o) my_incl += n;
        }
        if (lane == 31) s_wt[wid] = my_incl;
    }
    for (int i = t; i < 2048; i += 512) s_hist[i] = 0;
    __syncthreads();
    if (t < SPB) {
        unsigned off = 0;
#pragma unroll
        for (int w = 0; w < 4; w++) off += (w < wid) ? s_wt[w] : 0u;
        s_dst[t] = off + my_incl - my_c;
    }
    __syncthreads();
    unsigned cnt = s_dst[SPB - 1] + s_c[SPB - 1];
    if (t == 0 && cnt) atomicAdd(&g_tcnt[bg & 31], cnt);
    if (cnt == 0) {
        if (t == 0) g_inv[bg] = 1.0f;
        return;
    }
    bool fits = (cnt <= SBUF);

    // fused gather + level-1 histogram (bins = key >> 21)
    for (int s = wid; s < SPB; s += 16) {
        unsigned c = s_c[s];
        const unsigned* src = g_keys + (unsigned)(b * SPB + s) * 1024u + s_off[s];
        unsigned d = s_dst[s];
        for (unsigned j = lane; j < c; j += 32u) {
            unsigned key = src[j];
            atomicAdd(&s_hist[key >> 21], 1u);
            unsigned d2 = d + j;
            if (d2 < SBUF) s_buf[d2] = key;
        }
    }
    __syncthreads();

    // scan + pick helper over s_hist (nbins = 2048 or 1024), rank kk
    auto scan_pick = [&](int nbins, unsigned kk) {
        int per = nbins >> 9;                 // 4 or 2 bins per thread
        unsigned hh[4] = {0u, 0u, 0u, 0u};
        unsigned sum = 0;
        for (int j = 0; j < per; j++) { hh[j] = s_hist[t * per + j]; sum += hh[j]; }
        unsigned incl = sum;
#pragma unroll
        for (int o = 1; o < 32; o <<= 1) {
            unsigned n = __shfl_up_sync(0xffffffffu, incl, o);
            if (lane >= o) incl += n;
        }
        if (lane == 31) s_wsum[wid] = incl;
        __syncthreads();
        unsigned off = 0;
#pragma unroll
        for (int w = 0; w < 16; w++) off += (w < wid) ? s_wsum[w] : 0u;
        incl += off;
        unsigned excl = incl - sum;
        if (kk >= excl && kk < incl) {
            unsigned r = kk - excl;
            for (int j = 0; j < per; j++) {
                if (r < hh[j]) { sh_sel = (unsigned)(t * per + j); sh_k = r; sh_n = hh[j]; break; }
                r -= hh[j];
            }
        }
        __syncthreads();
    };

    unsigned k = (cnt - 1u) >> 1;            // lower median rank
    scan_pick(2048, k);
    unsigned sel0 = sh_sel; k = sh_k;
    unsigned ncand = sh_n;
    bool fits2 = (ncand <= CCAP);

    // collect candidates with top-11 == sel0 (ballot append)
    if (t == 0) sh_app = 0;
    __syncthreads();
    if (fits2) {
        if (fits) {
            unsigned lim = (cnt + 511u) & ~511u;
            for (unsigned i = t; i < lim; i += 512u) {
                bool ok = (i < cnt) && ((s_buf[i] >> 21) == sel0);
                unsigned key = ok ? s_buf[i] : 0u;
                unsigned bal = __ballot_sync(0xffffffffu, ok);
                unsigned base = 0;
                if (lane == 0 && bal) base = atomicAdd(&sh_app, (unsigned)__popc(bal));
                base = __shfl_sync(0xffffffffu, base, 0);
                if (ok) s_cand[base + __popc(bal & ((1u << lane) - 1u))] = key;
            }
        } else {
            for (int s = wid; s < SPB; s += 16) {
                unsigned c = s_c[s];
                const unsigned* src = g_keys + (unsigned)(b * SPB + s) * 1024u + s_off[s];
                unsigned lim = (c + 31u) & ~31u;
                for (unsigned j = lane; j < lim; j += 32u) {
                    bool ok = (j < c) && ((src[j] >> 21) == sel0);
                    unsigned key = ok ? src[j] : 0u;
                    unsigned bal = __ballot_sync(0xffffffffu, ok);
                    unsigned base = 0;
                    if (lane == 0 && bal) base = atomicAdd(&sh_app, (unsigned)__popc(bal));
                    base = __shfl_sync(0xffffffffu, base, 0);
                    if (ok) s_cand[base + __popc(bal & ((1u << lane) - 1u))] = key;
                }
            }
        }
    }
    __syncthreads();

    // level 2: bins = (key >> 10) & 2047 among candidates
    for (int i = t; i < 2048; i += 512) s_hist[i] = 0;
    __syncthreads();
    if (fits2) {
        for (unsigned i = t; i < ncand; i += 512u)
            atomicAdd(&s_hist[(s_cand[i] >> 10) & 2047u], 1u);
    } else if (fits) {
        for (unsigned i = t; i < cnt; i += 512u) {
            unsigned key = s_buf[i];
            if ((key >> 21) == sel0) atomicAdd(&s_hist[(key >> 10) & 2047u], 1u);
        }
    } else {
        for (int s = wid; s < SPB; s += 16) {
            unsigned c = s_c[s];
            const unsigned* src = g_keys + (unsigned)(b * SPB + s) * 1024u + s_off[s];
            for (unsigned j = lane; j < c; j += 32u) {
                unsigned key = src[j];
                if ((key >> 21) == sel0) atomicAdd(&s_hist[(key >> 10) & 2047u], 1u);
            }
        }
    }
    __syncthreads();
    scan_pick(2048, k);
    unsigned sel1 = sh_sel; k = sh_k;
    unsigned pfx22 = (sel0 << 11) | sel1;    // top 22 bits of the median key

    // level 3: bins = key & 1023 among candidates with (key >> 10) == pfx22
    for (int i = t; i < 1024; i += 512) s_hist[i] = 0;
    __syncthreads();
    if (fits2) {
        for (unsigned i = t; i < ncand; i += 512u) {
            unsigned key = s_cand[i];
            if ((key >> 10) == pfx22) atomicAdd(&s_hist[key & 1023u], 1u);
        }
    } else if (fits) {
        for (unsigned i = t; i < cnt; i += 512u) {
            unsigned key = s_buf[i];
            if ((key >> 10) == pfx22) atomicAdd(&s_hist[key & 1023u], 1u);
        }
    } else {
        for (int s = wid; s < SPB; s += 16) {
            unsigned c = s_c[s];
            const unsigned* src = g_keys + (unsigned)(b * SPB + s) * 1024u + s_off[s];
            for (unsigned j = lane; j < c; j += 32u) {
                unsigned key = src[j];
                if ((key >> 10) == pfx22) atomicAdd(&s_hist[key & 1023u], 1u);
            }
        }
    }
    __syncthreads();
    scan_pick(1024, k);

    if (t == 0) {
        unsigned kk = (pfx22 << 10) | sh_sel;
        unsigned ub = (kk & 0x80000000u) ? (kk & 0x7fffffffu) : ~kk;
        float med = __uint_as_float(ub);
        if (!isfinite(med)) med = 1.0f;      // nan_to_num semantics
        float ns = fmaxf(fabsf(med), 1e-6f);
        g_inv[bg] = 1.0f / ns;
    }
}

// ---------------- K3: branchless fused loss + reduction + last-block finalize/reset ----------------
__global__ void k_loss(const float* __restrict__ pred, const float* __restrict__ target,
                       float* __restrict__ out) {
    __shared__ float sinv2[32];              // [0..15]=0 (invalid), [16..31]=1/norm
    __shared__ float swarp[8];
    __shared__ int s_flag;
    int b = blockIdx.x >> 7;
    if (threadIdx.x < 32)
        sinv2[threadIdx.x] = (threadIdx.x >= 16) ? g_inv[b * GG + (threadIdx.x & 15)] : 0.f;
    __syncthreads();
    unsigned p0 = blockIdx.x * 1024u + threadIdx.x * 4u;   // 4 consecutive points/thread
    unsigned mg = __ldg(&g_mg[p0 >> 2]);
    const float4* pp = reinterpret_cast<const float4*>(pred + 3u * p0);
    const float4* tt = reinterpret_cast<const float4*>(target + 3u * p0);
    float4 pa = pp[0], pb = pp[1], pc = pp[2];
    float4 ta = tt[0], tb = tt[1], tc = tt[2];
    float pr[12] = {pa.x, pa.y, pa.z, pa.w, pb.x, pb.y, pb.z, pb.w, pc.x, pc.y, pc.z, pc.w};
    float tr[12] = {ta.x, ta.y, ta.z, ta.w, tb.x, tb.y, tb.z, tb.w, tc.x, tc.y, tc.z, tc.w};
    float acc = 0.f;
#pragma unroll
    for (int e = 0; e < 4; e++) {
        float inv = sinv2[(mg >> (8 * e)) & 0xFFu];   // 0 for invalid -> contributes 0
#pragma unroll
        for (int c = 0; c < 3; c++) {
            float p = pr[e * 3 + c] * inv;
            float t = tr[e * 3 + c] * inv;
            float u = fabsf(p); if (!(u <= 3.0e38f)) u = 0.f;   // nan_to_num
            float v = fabsf(t); if (!(v <= 3.0e38f)) v = 0.f;
            // |s_p*log1p(u) - s_t*log1p(v)| : same sign -> |log((1+u)/(1+v))|, diff -> log((1+u)(1+v))
            float a = 1.f + u, q = 1.f + v;
            bool same = (__float_as_uint(p) >> 31) == (__float_as_uint(t) >> 31);
            float r = same ? __fdividef(a, q) : a * q;
            acc += fabsf(__logf(r));
        }
    }
#pragma unroll
    for (int o = 16; o; o >>= 1) acc += __shfl_down_sync(0xffffffffu, acc, o);
    if ((threadIdx.x & 31) == 0) swarp[threadIdx.x >> 5] = acc;
    __syncthreads();
    if (threadIdx.x == 0) {
        float s = 0.f;
#pragma unroll
        for (int w = 0; w < 8; w++) s += swarp[w];
        atomicAdd(&g_psum[blockIdx.x & 31], (double)s);
        __threadfence();
        unsigned d = atomicAdd(&g_done, 1u);
        s_flag = (d == gridDim.x - 1u);
    }
    __syncthreads();
    if (s_flag) {
        if (threadIdx.x == 0) {
            unsigned total = 0;
#pragma unroll
            for (int j = 0; j < 32; j++) total += g_tcnt[j];
            double ssum = 0.0;
#pragma unroll
            for (int j = 0; j < 32; j++) ssum += g_psum[j];
            out[0] = (float)(ssum / (3.0 * (double)total + 1e-6));
        }
        __syncthreads();
        // restore scratch to all-zero for the next (graph-replayed) launch
        if (threadIdx.x < 32) { g_psum[threadIdx.x] = 0.0; g_tcnt[threadIdx.x] = 0u; }
        if (threadIdx.x == 0) g_done = 0u;
    }
}

extern "C" void kernel_launch(void* const* d_in, const int* in_sizes, int n_in,
                              void* d_out, int out_size) {
    const float* pred   = (const float*)d_in[0];
    const float* target = (const float*)d_in[1];
    const int*   mask   = (const int*)d_in[2];
    const int*   groups = (const int*)d_in[3];
    float* out = (float*)d_out;
    (void)in_sizes; (void)n_in; (void)out_size;

    k_scatter<<<NBLK, 256>>>(target, mask, groups);
    k_select <<<NGB,  512>>>();
    k_loss   <<<NBLK, 256>>>(pred, target, out);
}

// round 17
// speedup vs baseline: 1.0760x; 1.0101x over previous
#include <cuda_runtime.h>
#include <math.h>

#define BB 16
#define NN 131072
#define GG 16
#define BN (BB*NN)
#define NGB (BB*GG)          // 256 (b,g) pairs
#define NBLK 2048            // scatter blocks (128 per batch)
#define SPB  128             // slabs (scatter blocks) per batch
#define SBUF 6144            // smem key buffer (expected cnt ~4096, >30 sigma margin)
#define CCAP 2048            // candidate cap (expected ~300, huge margin)

// ---------------- scratch (device globals; zero at load, re-zeroed by finalizer) ----------------
__device__ unsigned g_keys[BN];          // per-block slabs of group-sorted keys (4KB each)
__device__ unsigned g_blkcnt[NBLK * GG]; // per-(block,group) counts (overwritten every launch)
__device__ unsigned g_mg[BN / 4];        // packed (valid<<4)|group, one byte/point
__device__ float    g_inv[NGB];          // 1 / clamp(|median|, eps)
__device__ double   g_psum[32];          // distributed loss partials
__device__ unsigned g_tcnt[32];          // distributed valid-count partials
__device__ unsigned g_done;              // loss block completion counter

// order-preserving map f32 -> u32 (ascending)
__device__ __forceinline__ unsigned key_of(float z) {
    unsigned u = __float_as_uint(z);
    return (u & 0x80000000u) ? ~u : (u | 0x80000000u);
}

// ---------------- K1: slab scatter + L2 prewarm of pred for k_loss ----------------
__global__ void k_scatter(const float* __restrict__ target, const int* __restrict__ mask,
                          const int* __restrict__ groups, const float* __restrict__ pred) {
    __shared__ unsigned s_cnt[32][16];     // slot = wid*4 + e
    __shared__ unsigned s_gstart[17];      // block-local group starts (+ total)
    __shared__ uint4    s_keys4[256];      // staged keys grouped by bucket (aliased)
    unsigned* s_keys = reinterpret_cast<unsigned*>(s_keys4);
    unsigned p0 = blockIdx.x * 1024u + threadIdx.x * 4u;  // 4 consecutive points/thread
    int wid = threadIdx.x >> 5, lane = threadIdx.x & 31;

    ((unsigned*)s_cnt)[threadIdx.x] = 0;
    ((unsigned*)s_cnt)[256 + threadIdx.x] = 0;

    // L2 prewarm: pull this block's future k_loss pred stream (12KB = 96 lines)
    // into L2 using scatter's spare DRAM bandwidth. No registers held, no dependency.
    {
        const char* pb = reinterpret_cast<const char*>(pred + 3ull * blockIdx.x * 1024ull);
        if (threadIdx.x < 96)
            asm volatile("prefetch.global.L2 [%0];" :: "l"(pb + threadIdx.x * 128) : "memory");
    }

    int4 m4 = *reinterpret_cast<const int4*>(mask + p0);
    int4 g4 = *reinterpret_cast<const int4*>(groups + p0);
    const float4* tt = reinterpret_cast<const float4*>(target + 3u * p0);
    float4 t0 = tt[0], t1 = tt[1], t2 = tt[2];
    int   m[4] = {m4.x, m4.y, m4.z, m4.w};
    int   g[4] = {g4.x & 15, g4.y & 15, g4.z & 15, g4.w & 15};
    float z[4] = {t0.z, t1.y, t2.x, t2.w};

    unsigned mg = 0;
#pragma unroll
    for (int e = 0; e < 4; e++)
        mg |= ((m[e] ? 0x10u : 0u) | (unsigned)g[e]) << (8 * e);
    g_mg[p0 >> 2] = mg;
    __syncthreads();   // s_cnt zero visible

    unsigned peers[4];
#pragma unroll
    for (int e = 0; e < 4; e++) {
        unsigned tag = m[e] ? (unsigned)g[e] : 0xFFFFFFFFu;
        peers[e] = __match_any_sync(0xffffffffu, tag);
        if (m[e] && lane == (__ffs(peers[e]) - 1))
            s_cnt[wid * 4 + e][g[e]] = __popc(peers[e]);
    }
    __syncthreads();

    if (threadIdx.x < 16) {
        unsigned run = 0;
#pragma unroll
        for (int s = 0; s < 32; s++) {
            unsigned c = s_cnt[s][threadIdx.x];
            s_cnt[s][threadIdx.x] = run;
            run += c;
        }
        unsigned incl = run;
#pragma unroll
        for (int o = 1; o < 16; o <<= 1) {
            unsigned n = __shfl_up_sync(0x0000FFFFu, incl, o);
            if (lane >= o) incl += n;
        }
        s_gstart[threadIdx.x] = incl - run;
        if (threadIdx.x == 15) s_gstart[16] = incl;
        g_blkcnt[blockIdx.x * GG + threadIdx.x] = run;   // unconditional: no reset needed
    }
    __syncthreads();

#pragma unroll
    for (int e = 0; e < 4; e++) {
        if (m[e]) {
            unsigned local = s_gstart[g[e]] + s_cnt[wid * 4 + e][g[e]]
                           + __popc(peers[e] & ((1u << lane) - 1u));
            s_keys[local] = key_of(z[e]);
        }
    }
    __syncthreads();

    // straight coalesced copy of the staged (group-sorted) slab
    unsigned nvec = (s_gstart[16] + 3u) >> 2;
    uint4* dst = reinterpret_cast<uint4*>(g_keys + blockIdx.x * 1024u);
    for (unsigned i = threadIdx.x; i < nvec; i += 256u) dst[i] = s_keys4[i];
}

// ---------------- K2: fused gather + 2048-bin radix (11/11/10 bits) ----------------
__global__ void k_select() {
    __shared__ unsigned s_off[SPB], s_c[SPB], s_dst[SPB];
    __shared__ unsigned s_hist[2048];
    __shared__ unsigned s_wsum[16];
    __shared__ unsigned s_wt[4];
    __shared__ unsigned s_buf[SBUF];
    __shared__ unsigned s_cand[CCAP];
    __shared__ unsigned sh_sel, sh_k, sh_n, sh_app;
    int bg = blockIdx.x;
    int b = bg >> 4, g = bg & 15;
    int t = threadIdx.x, lane = t & 31, wid = t >> 5;

    // per-slab run offset/count + destination prefix (128 slabs, warps 0..3)
    unsigned my_incl = 0, my_c = 0;
    if (t < SPB) {
        const uint4* p = reinterpret_cast<const uint4*>(g_blkcnt + (unsigned)(b * SPB + t) * GG);
        uint4 c0 = p[0], c1 = p[1], c2 = p[2], c3 = p[3];
        unsigned cc[16] = {c0.x, c0.y, c0.z, c0.w, c1.x, c1.y, c1.z, c1.w,
                           c2.x, c2.y, c2.z, c2.w, c3.x, c3.y, c3.z, c3.w};
        unsigned start = 0;
        for (int j = 0; j < g; j++) start += cc[j];   // g uniform across block
        my_c = cc[g];
        s_off[t] = start;
        s_c[t] = my_c;
        my_incl = my_c;
#pragma unroll
        for (int o = 1; o < 32; o <<= 1) {
            unsigned n = __shfl_up_sync(0xffffffffu, my_incl, o);
            if (lane >= o) my_incl += n;
        }
        if (lane == 31) s_wt[wid] = my_incl;
    }
    for (int i = t; i < 2048; i += 512) s_hist[i] = 0;
    __syncthreads();
    if (t < SPB) {
        unsigned off = 0;
#pragma unroll
        for (int w = 0; w < 4; w++) off += (w < wid) ? s_wt[w] : 0u;
        s_dst[t] = off + my_incl - my_c;
    }
    __syncthreads();
    unsigned cnt = s_dst[SPB - 1] + s_c[SPB - 1];
    if (t == 0 && cnt) atomicAdd(&g_tcnt[bg & 31], cnt);
    if (cnt == 0) {
        if (t == 0) g_inv[bg] = 1.0f;
        return;
    }
    bool fits = (cnt <= SBUF);

    // fused gather + level-1 histogram (bins = key >> 21)
    for (int s = wid; s < SPB; s += 16) {
        unsigned c = s_c[s];
        const unsigned* src = g_keys + (unsigned)(b * SPB + s) * 1024u + s_off[s];
        unsigned d = s_dst[s];
        for (unsigned j = lane; j < c; j += 32u) {
            unsigned key = src[j];
            atomicAdd(&s_hist[key >> 21], 1u);
            unsigned d2 = d + j;
            if (d2 < SBUF) s_buf[d2] = key;
        }
    }
    __syncthreads();

    // scan + pick helper over s_hist (nbins = 2048 or 1024), rank kk
    auto scan_pick = [&](int nbins, unsigned kk) {
        int per = nbins >> 9;                 // 4 or 2 bins per thread
        unsigned hh[4] = {0u, 0u, 0u, 0u};
        unsigned sum = 0;
        for (int j = 0; j < per; j++) { hh[j] = s_hist[t * per + j]; sum += hh[j]; }
        unsigned incl = sum;
#pragma unroll
        for (int o = 1; o < 32; o <<= 1) {
            unsigned n = __shfl_up_sync(0xffffffffu, incl, o);
            if (lane >= o) incl += n;
        }
        if (lane == 31) s_wsum[wid] = incl;
        __syncthreads();
        unsigned off = 0;
#pragma unroll
        for (int w = 0; w < 16; w++) off += (w < wid) ? s_wsum[w] : 0u;
        incl += off;
        unsigned excl = incl - sum;
        if (kk >= excl && kk < incl) {
            unsigned r = kk - excl;
            for (int j = 0; j < per; j++) {
                if (r < hh[j]) { sh_sel = (unsigned)(t * per + j); sh_k = r; sh_n = hh[j]; break; }
                r -= hh[j];
            }
        }
        __syncthreads();
    };

    unsigned k = (cnt - 1u) >> 1;            // lower median rank
    scan_pick(2048, k);
    unsigned sel0 = sh_sel; k = sh_k;
    unsigned ncand = sh_n;
    bool fits2 = (ncand <= CCAP);

    // collect candidates with top-11 == sel0 (ballot append)
    if (t == 0) sh_app = 0;
    __syncthreads();
    if (fits2) {
        if (fits) {
            unsigned lim = (cnt + 511u) & ~511u;
            for (unsigned i = t; i < lim; i += 512u) {
                bool ok = (i < cnt) && ((s_buf[i] >> 21) == sel0);
                unsigned key = ok ? s_buf[i] : 0u;
                unsigned bal = __ballot_sync(0xffffffffu, ok);
                unsigned base = 0;
                if (lane == 0 && bal) base = atomicAdd(&sh_app, (unsigned)__popc(bal));
                base = __shfl_sync(0xffffffffu, base, 0);
                if (ok) s_cand[base + __popc(bal & ((1u << lane) - 1u))] = key;
            }
        } else {
            for (int s = wid; s < SPB; s += 16) {
                unsigned c = s_c[s];
                const unsigned* src = g_keys + (unsigned)(b * SPB + s) * 1024u + s_off[s];
                unsigned lim = (c + 31u) & ~31u;
                for (unsigned j = lane; j < lim; j += 32u) {
                    bool ok = (j < c) && ((src[j] >> 21) == sel0);
                    unsigned key = ok ? src[j] : 0u;
                    unsigned bal = __ballot_sync(0xffffffffu, ok);
                    unsigned base = 0;
                    if (lane == 0 && bal) base = atomicAdd(&sh_app, (unsigned)__popc(bal));
                    base = __shfl_sync(0xffffffffu, base, 0);
                    if (ok) s_cand[base + __popc(bal & ((1u << lane) - 1u))] = key;
                }
            }
        }
    }
    __syncthreads();

    // level 2: bins = (key >> 10) & 2047 among candidates
    for (int i = t; i < 2048; i += 512) s_hist[i] = 0;
    __syncthreads();
    if (fits2) {
        for (unsigned i = t; i < ncand; i += 512u)
            atomicAdd(&s_hist[(s_cand[i] >> 10) & 2047u], 1u);
    } else if (fits) {
        for (unsigned i = t; i < cnt; i += 512u) {
            unsigned key = s_buf[i];
            if ((key >> 21) == sel0) atomicAdd(&s_hist[(key >> 10) & 2047u], 1u);
        }
    } else {
        for (int s = wid; s < SPB; s += 16) {
            unsigned c = s_c[s];
            const unsigned* src = g_keys + (unsigned)(b * SPB + s) * 1024u + s_off[s];
            for (unsigned j = lane; j < c; j += 32u) {
                unsigned key = src[j];
                if ((key >> 21) == sel0) atomicAdd(&s_hist[(key >> 10) & 2047u], 1u);
            }
        }
    }
    __syncthreads();
    scan_pick(2048, k);
    unsigned sel1 = sh_sel; k = sh_k;
    unsigned pfx22 = (sel0 << 11) | sel1;    // top 22 bits of the median key

    // level 3: bins = key & 1023 among candidates with (key >> 10) == pfx22
    for (int i = t; i < 1024; i += 512) s_hist[i] = 0;
    __syncthreads();
    if (fits2) {
        for (unsigned i = t; i < ncand; i += 512u) {
            unsigned key = s_cand[i];
            if ((key >> 10) == pfx22) atomicAdd(&s_hist[key & 1023u], 1u);
        }
    } else if (fits) {
        for (unsigned i = t; i < cnt; i += 512u) {
            unsigned key = s_buf[i];
            if ((key >> 10) == pfx22) atomicAdd(&s_hist[key & 1023u], 1u);
        }
    } else {
        for (int s = wid; s < SPB; s += 16) {
            unsigned c = s_c[s];
            const unsigned* src = g_keys + (unsigned)(b * SPB + s) * 1024u + s_off[s];
            for (unsigned j = lane; j < c; j += 32u) {
                unsigned key = src[j];
                if ((key >> 10) == pfx22) atomicAdd(&s_hist[key & 1023u], 1u);
            }
        }
    }
    __syncthreads();
    scan_pick(1024, k);

    if (t == 0) {
        unsigned kk = (pfx22 << 10) | sh_sel;
        unsigned ub = (kk & 0x80000000u) ? (kk & 0x7fffffffu) : ~kk;
        float med = __uint_as_float(ub);
        if (!isfinite(med)) med = 1.0f;      // nan_to_num semantics
        float ns = fmaxf(fabsf(med), 1e-6f);
        g_inv[bg] = 1.0f / ns;
    }
}

// ---------------- K3: branchless fused loss + reduction + last-block finalize/reset ----------------
__global__ void k_loss(const float* __restrict__ pred, const float* __restrict__ target,
                       float* __restrict__ out) {
    __shared__ float sinv2[32];              // [0..15]=0 (invalid), [16..31]=1/norm
    __shared__ float swarp[8];
    __shared__ int s_flag;
    int b = blockIdx.x >> 7;
    if (threadIdx.x < 32)
        sinv2[threadIdx.x] = (threadIdx.x >= 16) ? g_inv[b * GG + (threadIdx.x & 15)] : 0.f;
    __syncthreads();
    unsigned p0 = blockIdx.x * 1024u + threadIdx.x * 4u;   // 4 consecutive points/thread
    unsigned mg = __ldg(&g_mg[p0 >> 2]);
    const float4* pp = reinterpret_cast<const float4*>(pred + 3u * p0);
    const float4* tt = reinterpret_cast<const float4*>(target + 3u * p0);
    float4 pa = pp[0], pb = pp[1], pc = pp[2];
    float4 ta = tt[0], tb = tt[1], tc = tt[2];
    float pr[12] = {pa.x, pa.y, pa.z, pa.w, pb.x, pb.y, pb.z, pb.w, pc.x, pc.y, pc.z, pc.w};
    float tr[12] = {ta.x, ta.y, ta.z, ta.w, tb.x, tb.y, tb.z, tb.w, tc.x, tc.y, tc.z, tc.w};
    float acc = 0.f;
#pragma unroll
    for (int e = 0; e < 4; e++) {
        float inv = sinv2[(mg >> (8 * e)) & 0xFFu];   // 0 for invalid -> contributes 0
#pragma unroll
        for (int c = 0; c < 3; c++) {
            float p = pr[e * 3 + c] * inv;
            float t = tr[e * 3 + c] * inv;
            float u = fabsf(p); if (!(u <= 3.0e38f)) u = 0.f;   // nan_to_num
            float v = fabsf(t); if (!(v <= 3.0e38f)) v = 0.f;
            // |s_p*log1p(u) - s_t*log1p(v)| : same sign -> |log((1+u)/(1+v))|, diff -> log((1+u)(1+v))
            float a = 1.f + u, q = 1.f + v;
            bool same = (__float_as_uint(p) >> 31) == (__float_as_uint(t) >> 31);
            float r = same ? __fdividef(a, q) : a * q;
            acc += fabsf(__logf(r));
        }
    }
#pragma unroll
    for (int o = 16; o; o >>= 1) acc += __shfl_down_sync(0xffffffffu, acc, o);
    if ((threadIdx.x & 31) == 0) swarp[threadIdx.x >> 5] = acc;
    __syncthreads();
    if (threadIdx.x == 0) {
        float s = 0.f;
#pragma unroll
        for (int w = 0; w < 8; w++) s += swarp[w];
        atomicAdd(&g_psum[blockIdx.x & 31], (double)s);
        __threadfence();
        unsigned d = atomicAdd(&g_done, 1u);
        s_flag = (d == gridDim.x - 1u);
    }
    __syncthreads();
    if (s_flag) {
        if (threadIdx.x == 0) {
            unsigned total = 0;
#pragma unroll
            for (int j = 0; j < 32; j++) total += g_tcnt[j];
            double ssum = 0.0;
#pragma unroll
            for (int j = 0; j < 32; j++) ssum += g_psum[j];
            out[0] = (float)(ssum / (3.0 * (double)total + 1e-6));
        }
        __syncthreads();
        // restore scratch to all-zero for the next (graph-replayed) launch
        if (threadIdx.x < 32) { g_psum[threadIdx.x] = 0.0; g_tcnt[threadIdx.x] = 0u; }
        if (threadIdx.x == 0) g_done = 0u;
    }
}

extern "C" void kernel_launch(void* const* d_in, const int* in_sizes, int n_in,
                              void* d_out, int out_size) {
    const float* pred   = (const float*)d_in[0];
    const float* target = (const float*)d_in[1];
    const int*   mask   = (const int*)d_in[2];
    const int*   groups = (const int*)d_in[3];
    float* out = (float*)d_out;
    (void)in_sizes; (void)n_in; (void)out_size;

    k_scatter<<<NBLK, 256>>>(target, mask, groups, pred);
    k_select <<<NGB,  512>>>();
    k_loss   <<<NBLK, 256>>>(pred, target, out);
}